// round 1
// baseline (speedup 1.0000x reference)
#include <cuda_runtime.h>
#include <math.h>

#define SEQ    2048
#define BATCH  2
#define DM     1024
#define NH     16
#define HD     64
#define DFF    4096
#define SB     (SEQ*BATCH)          /* 4096 rows */
#define LN_EPS 1e-5f

// ---------------- scratch (static __device__, allocation-rule safe) ---------
__device__ float g_q [SB*DM];
__device__ float g_k [SB*DM];
__device__ float g_v [SB*DM];
__device__ float g_att[SB*DM];
__device__ float g_x [SB*DM];
__device__ float g_ff[SB*DFF];

// ---------------- generic tiled SGEMM: C = A@B + bias (opt. relu) ----------
// A: [M,K] row-major, B: [K,N] row-major, C: [M,N]. M,N % 128 == 0, K % 16 == 0.
template<int RELU>
__global__ __launch_bounds__(256)
void sgemm(const float* __restrict__ A, const float* __restrict__ B,
           const float* __restrict__ bias, float* __restrict__ C,
           int M, int N, int K)
{
    __shared__ float As[16][128];
    __shared__ float Bs[16][128];
    const int tid = threadIdx.x;
    const int tx = tid & 15, ty = tid >> 4;
    const int bm = blockIdx.y * 128, bn = blockIdx.x * 128;

    float acc[8][8] = {};

    for (int kt = 0; kt < K; kt += 16) {
        #pragma unroll
        for (int u = 0; u < 2; u++) {
            int f = tid + u * 256;
            // A tile: 128 rows x 16 k  (512 float4)
            int arow = f >> 2, k4 = f & 3;
            float4 va = *(const float4*)(A + (size_t)(bm + arow) * K + kt + k4 * 4);
            As[k4*4+0][arow] = va.x;
            As[k4*4+1][arow] = va.y;
            As[k4*4+2][arow] = va.z;
            As[k4*4+3][arow] = va.w;
            // B tile: 16 rows x 128 cols (512 float4)
            int brow = f >> 5, c4 = f & 31;
            *(float4*)&Bs[brow][c4*4] =
                *(const float4*)(B + (size_t)(kt + brow) * N + bn + c4 * 4);
        }
        __syncthreads();

        #pragma unroll
        for (int kk = 0; kk < 16; kk++) {
            float a[8], b[8];
            *(float4*)(a)   = *(float4*)&As[kk][ty*8];
            *(float4*)(a+4) = *(float4*)&As[kk][ty*8+4];
            *(float4*)(b)   = *(float4*)&Bs[kk][tx*8];
            *(float4*)(b+4) = *(float4*)&Bs[kk][tx*8+4];
            #pragma unroll
            for (int i = 0; i < 8; i++)
                #pragma unroll
                for (int j = 0; j < 8; j++)
                    acc[i][j] += a[i] * b[j];
        }
        __syncthreads();
    }

    #pragma unroll
    for (int i = 0; i < 8; i++) {
        int row = bm + ty*8 + i;
        #pragma unroll
        for (int j = 0; j < 8; j += 4) {
            int col = bn + tx*8 + j;
            float4 r;
            r.x = acc[i][j+0] + bias[col+0];
            r.y = acc[i][j+1] + bias[col+1];
            r.z = acc[i][j+2] + bias[col+2];
            r.w = acc[i][j+3] + bias[col+3];
            if (RELU) {
                r.x = fmaxf(r.x, 0.f); r.y = fmaxf(r.y, 0.f);
                r.z = fmaxf(r.z, 0.f); r.w = fmaxf(r.w, 0.f);
            }
            *(float4*)(C + (size_t)row * N + col) = r;
        }
    }
}

// ---------------- RoPE (interleaved pairs), applied in-place to Q and K -----
__global__ void rope_kernel(float* __restrict__ Q, float* __restrict__ K)
{
    int idx = blockIdx.x * blockDim.x + threadIdx.x;   // pair index
    if (idx >= SB * DM / 2) return;
    int flat = idx * 2;                 // even element index in [S,B,E] flat
    int d    = flat % HD;               // even dim within head (2i)
    int s    = flat / (BATCH * DM);     // sequence position

    // inv_freq = theta^(-(2i)/HD) ; angle = s * inv_freq
    float angle = (float)s * powf(10000.0f, -(float)d / (float)HD);
    float c = cosf(angle), sn = sinf(angle);

    float q0 = Q[flat], q1 = Q[flat+1];
    Q[flat]   = q0 * c - q1 * sn;
    Q[flat+1] = q1 * c + q0 * sn;
    float k0 = K[flat], k1 = K[flat+1];
    K[flat]   = k0 * c - k1 * sn;
    K[flat+1] = k1 * c + k0 * sn;
}

// ---------------- flash-style attention: 128 q rows / block ----------------
// Q,K,V,O in [S, B, E] flat layout; head (b,h) slice starts at b*DM + h*HD,
// row stride BATCH*DM.
__global__ __launch_bounds__(128)
void attn_kernel(const float* __restrict__ Q, const float* __restrict__ K,
                 const float* __restrict__ V, float* __restrict__ O)
{
    const int qt = blockIdx.x;           // 0..15  (q tile of 128)
    const int h  = blockIdx.y;           // head
    const int b  = blockIdx.z;           // batch
    const int stride = BATCH * DM;
    const int base   = b * DM + h * HD;
    const int t  = threadIdx.x;
    const int q0 = qt * 128;

    __shared__ float sm[2 * 64 * 65];    // K/V tiles; also Q staging (128*65)
    float* Ks = sm;
    float* Vs = sm + 64 * 65;

    // stage the Q tile through smem (coalesced gmem -> conflict-free row read)
    for (int i = t; i < 128 * 64; i += 128) {
        int r = i >> 6, d = i & 63;
        sm[r * 65 + d] = Q[(size_t)(q0 + r) * stride + base + d];
    }
    __syncthreads();
    float q[64];
    #pragma unroll
    for (int d = 0; d < 64; d++) q[d] = sm[t * 65 + d];
    __syncthreads();

    float o[64];
    #pragma unroll
    for (int d = 0; d < 64; d++) o[d] = 0.f;
    float m = -1e30f, l = 0.f;

    for (int kt = 0; kt < SEQ; kt += 64) {
        for (int i = t; i < 64 * 64; i += 128) {
            int r = i >> 6, d = i & 63;
            Ks[r * 65 + d] = K[(size_t)(kt + r) * stride + base + d];
            Vs[r * 65 + d] = V[(size_t)(kt + r) * stride + base + d];
        }
        __syncthreads();

        for (int j = 0; j < 64; j++) {
            float s = 0.f;
            #pragma unroll
            for (int d = 0; d < 64; d++) s += q[d] * Ks[j * 65 + d];
            s *= 0.125f;                         // 1/sqrt(64)
            if (s > m) {
                float sc = __expf(m - s);
                l *= sc;
                #pragma unroll
                for (int d = 0; d < 64; d++) o[d] *= sc;
                m = s;
            }
            float p = __expf(s - m);
            l += p;
            #pragma unroll
            for (int d = 0; d < 64; d++) o[d] += p * Vs[j * 65 + d];
        }
        __syncthreads();
    }

    float inv = 1.f / l;
    #pragma unroll
    for (int d = 0; d < 64; d++)
        O[(size_t)(q0 + t) * stride + base + d] = o[d] * inv;
}

// ---------------- residual add + LayerNorm (one block per row) -------------
__global__ __launch_bounds__(256)
void add_ln_kernel(const float* __restrict__ A, const float* __restrict__ B,
                   const float* __restrict__ g, const float* __restrict__ bta,
                   float* __restrict__ out)
{
    const int row = blockIdx.x;
    const int tid = threadIdx.x;
    const float* a = A + (size_t)row * DM;
    const float* b = B + (size_t)row * DM;

    float v[4];
    float4 va = *(const float4*)(a + tid * 4);
    float4 vb = *(const float4*)(b + tid * 4);
    v[0] = va.x + vb.x; v[1] = va.y + vb.y;
    v[2] = va.z + vb.z; v[3] = va.w + vb.w;

    float sum = v[0] + v[1] + v[2] + v[3];
    float sq  = v[0]*v[0] + v[1]*v[1] + v[2]*v[2] + v[3]*v[3];

    #pragma unroll
    for (int off = 16; off; off >>= 1) {
        sum += __shfl_xor_sync(0xFFFFFFFF, sum, off);
        sq  += __shfl_xor_sync(0xFFFFFFFF, sq,  off);
    }
    __shared__ float ssum[8], ssq[8], sstat[2];
    if ((tid & 31) == 0) { ssum[tid >> 5] = sum; ssq[tid >> 5] = sq; }
    __syncthreads();
    if (tid == 0) {
        float ts = 0.f, tq = 0.f;
        #pragma unroll
        for (int i = 0; i < 8; i++) { ts += ssum[i]; tq += ssq[i]; }
        float mean = ts / (float)DM;
        float var  = tq / (float)DM - mean * mean;
        sstat[0] = mean;
        sstat[1] = rsqrtf(fmaxf(var, 0.f) + LN_EPS);
    }
    __syncthreads();
    float mean = sstat[0], inv = sstat[1];

    float4 vg = *(const float4*)(g   + tid * 4);
    float4 vB = *(const float4*)(bta + tid * 4);
    float4 r;
    r.x = (v[0] - mean) * inv * vg.x + vB.x;
    r.y = (v[1] - mean) * inv * vg.y + vB.y;
    r.z = (v[2] - mean) * inv * vg.z + vB.z;
    r.w = (v[3] - mean) * inv * vg.w + vB.w;
    *(float4*)(out + (size_t)row * DM + tid * 4) = r;
}

// ---------------------------------------------------------------------------
extern "C" void kernel_launch(void* const* d_in, const int* in_sizes, int n_in,
                              void* d_out, int out_size)
{
    const float* src  = (const float*)d_in[0];
    const float* q_w  = (const float*)d_in[1];
    const float* q_b  = (const float*)d_in[2];
    const float* k_w  = (const float*)d_in[3];
    const float* k_b  = (const float*)d_in[4];
    const float* v_w  = (const float*)d_in[5];
    const float* v_b  = (const float*)d_in[6];
    const float* w1   = (const float*)d_in[7];
    const float* b1   = (const float*)d_in[8];
    const float* w2   = (const float*)d_in[9];
    const float* b2   = (const float*)d_in[10];
    const float* ln1g = (const float*)d_in[11];
    const float* ln1b = (const float*)d_in[12];
    const float* ln2g = (const float*)d_in[13];
    const float* ln2b = (const float*)d_in[14];
    float* out = (float*)d_out;

    float *q, *k, *v, *att, *x, *ff;
    cudaGetSymbolAddress((void**)&q,   g_q);
    cudaGetSymbolAddress((void**)&k,   g_k);
    cudaGetSymbolAddress((void**)&v,   g_v);
    cudaGetSymbolAddress((void**)&att, g_att);
    cudaGetSymbolAddress((void**)&x,   g_x);
    cudaGetSymbolAddress((void**)&ff,  g_ff);

    dim3 gQKV(DM / 128, SB / 128);
    sgemm<0><<<gQKV, 256>>>(src, q_w, q_b, q, SB, DM, DM);
    sgemm<0><<<gQKV, 256>>>(src, k_w, k_b, k, SB, DM, DM);
    sgemm<0><<<gQKV, 256>>>(src, v_w, v_b, v, SB, DM, DM);

    rope_kernel<<<(SB * DM / 2 + 255) / 256, 256>>>(q, k);

    attn_kernel<<<dim3(SEQ / 128, NH, BATCH), 128>>>(q, k, v, att);

    add_ln_kernel<<<SB, 256>>>(src, att, ln1g, ln1b, x);

    sgemm<1><<<dim3(DFF / 128, SB / 128), 256>>>(x, w1, b1, ff, SB, DFF, DM);
    // reuse g_q for FFN output
    sgemm<0><<<dim3(DM / 128, SB / 128), 256>>>(ff, w2, b2, q, SB, DM, DFF);

    add_ln_kernel<<<SB, 256>>>(x, q, ln2g, ln2b, out);
}

// round 2
// speedup vs baseline: 1.4910x; 1.4910x over previous
#include <cuda_runtime.h>
#include <math.h>

#define SEQ    2048
#define BATCH  2
#define DM     1024
#define NH     16
#define HD     64
#define DFF    4096
#define SB     (SEQ*BATCH)          /* 4096 rows */
#define LN_EPS 1e-5f

// ---------------- scratch (static __device__, allocation-rule safe) ---------
__device__ float g_q [SB*DM];
__device__ float g_k [SB*DM];
__device__ float g_v [SB*DM];
__device__ float g_att[SB*DM];
__device__ float g_x [SB*DM];
__device__ float g_ff[SB*DFF];

// ---------------- helpers ---------------------------------------------------
__device__ __forceinline__ unsigned f2tf32(float x) {
    unsigned r;
    asm("cvt.rna.tf32.f32 %0, %1;" : "=r"(r) : "f"(x));
    return r;
}

__device__ __forceinline__ void cp16(void* smem, const void* gmem) {
    unsigned s = (unsigned)__cvta_generic_to_shared(smem);
    asm volatile("cp.async.cg.shared.global [%0], [%1], 16;" :: "r"(s), "l"(gmem));
}

__device__ __forceinline__ void mma_tf32(float c[4],
                                         unsigned a0, unsigned a1, unsigned a2, unsigned a3,
                                         unsigned b0, unsigned b1) {
    asm volatile(
        "mma.sync.aligned.m16n8k8.row.col.f32.tf32.tf32.f32 "
        "{%0,%1,%2,%3}, {%4,%5,%6,%7}, {%8,%9}, {%0,%1,%2,%3};"
        : "+f"(c[0]), "+f"(c[1]), "+f"(c[2]), "+f"(c[3])
        : "r"(a0), "r"(a1), "r"(a2), "r"(a3), "r"(b0), "r"(b1));
}

// ---------------- TF32 tensor-core GEMM: C = A@B + bias (opt relu) ----------
// A: [M,K] row-major, B: [K,N] row-major. M%128==0, N%128==0, K%16==0.
// Block 256 thr = 8 warps (4x2), warp tile 32x64, BK=16, 2-stage cp.async.
template<int RELU>
__global__ __launch_bounds__(256, 2)
void gemm_tf32(const float* __restrict__ A, const float* __restrict__ B,
               const float* __restrict__ bias, float* __restrict__ C,
               int M, int N, int K)
{
    __shared__ float As[2][128][20];   // [m][k], row stride 20 -> conflict-free frags
    __shared__ float Bs[2][16][136];   // [k][n], row stride 136 -> conflict-free frags

    const int tid  = threadIdx.x;
    const int warp = tid >> 5, lane = tid & 31;
    const int g = lane >> 2, t = lane & 3;
    const int wm = warp >> 1, wn = warp & 1;      // 4x2 warp grid
    const int bm = blockIdx.y * 128, bn = blockIdx.x * 128;

    float acc[2][8][4];
    #pragma unroll
    for (int i = 0; i < 2; i++)
        #pragma unroll
        for (int j = 0; j < 8; j++)
            #pragma unroll
            for (int r = 0; r < 4; r++) acc[i][j][r] = 0.f;

    const int KT = K / 16;

    // stage loader: A tile 128x16 (512 f4), B tile 16x128 (512 f4); 2 f4/thread each
    auto load_stage = [&](int s, int kt) {
        #pragma unroll
        for (int u = 0; u < 2; u++) {
            int f  = tid + u * 256;
            int ar = f >> 2, ak = (f & 3) * 4;
            cp16(&As[s][ar][ak], A + (size_t)(bm + ar) * K + kt + ak);
            int br = f >> 5, bc = (f & 31) * 4;
            cp16(&Bs[s][br][bc], B + (size_t)(kt + br) * N + bn + bc);
        }
        asm volatile("cp.async.commit_group;");
    };

    load_stage(0, 0);

    for (int kt = 0; kt < KT; kt++) {
        if (kt + 1 < KT) {
            load_stage((kt + 1) & 1, (kt + 1) * 16);
            asm volatile("cp.async.wait_group 1;");
        } else {
            asm volatile("cp.async.wait_group 0;");
        }
        __syncthreads();

        const int s = kt & 1;
        #pragma unroll
        for (int ks = 0; ks < 2; ks++) {
            const int k0 = ks * 8;
            unsigned a[2][4];
            #pragma unroll
            for (int mf = 0; mf < 2; mf++) {
                int m = wm * 32 + mf * 16 + g;
                a[mf][0] = f2tf32(As[s][m    ][k0 + t    ]);
                a[mf][1] = f2tf32(As[s][m + 8][k0 + t    ]);
                a[mf][2] = f2tf32(As[s][m    ][k0 + t + 4]);
                a[mf][3] = f2tf32(As[s][m + 8][k0 + t + 4]);
            }
            #pragma unroll
            for (int nf = 0; nf < 8; nf++) {
                int n = wn * 64 + nf * 8 + g;
                unsigned b0 = f2tf32(Bs[s][k0 + t    ][n]);
                unsigned b1 = f2tf32(Bs[s][k0 + t + 4][n]);
                mma_tf32(acc[0][nf], a[0][0], a[0][1], a[0][2], a[0][3], b0, b1);
                mma_tf32(acc[1][nf], a[1][0], a[1][1], a[1][2], a[1][3], b0, b1);
            }
        }
        __syncthreads();
    }

    // epilogue: bias (+relu), float2 stores
    #pragma unroll
    for (int mf = 0; mf < 2; mf++) {
        int r0 = bm + wm * 32 + mf * 16 + g;
        #pragma unroll
        for (int nf = 0; nf < 8; nf++) {
            int col = bn + wn * 64 + nf * 8 + t * 2;
            float2 bv = *(const float2*)(bias + col);
            float2 v0, v1;
            v0.x = acc[mf][nf][0] + bv.x; v0.y = acc[mf][nf][1] + bv.y;
            v1.x = acc[mf][nf][2] + bv.x; v1.y = acc[mf][nf][3] + bv.y;
            if (RELU) {
                v0.x = fmaxf(v0.x, 0.f); v0.y = fmaxf(v0.y, 0.f);
                v1.x = fmaxf(v1.x, 0.f); v1.y = fmaxf(v1.y, 0.f);
            }
            *(float2*)(C + (size_t)r0      * N + col) = v0;
            *(float2*)(C + (size_t)(r0 + 8) * N + col) = v1;
        }
    }
}

// ---------------- RoPE (interleaved pairs), applied in-place to Q and K -----
__global__ void rope_kernel(float* __restrict__ Q, float* __restrict__ K)
{
    int idx = blockIdx.x * blockDim.x + threadIdx.x;   // pair index
    if (idx >= SB * DM / 2) return;
    int flat = idx * 2;
    int d    = flat % HD;
    int s    = flat / (BATCH * DM);

    float angle = (float)s * powf(10000.0f, -(float)d / (float)HD);
    float c = cosf(angle), sn = sinf(angle);

    float q0 = Q[flat], q1 = Q[flat+1];
    Q[flat]   = q0 * c - q1 * sn;
    Q[flat+1] = q1 * c + q0 * sn;
    float k0 = K[flat], k1 = K[flat+1];
    K[flat]   = k0 * c - k1 * sn;
    K[flat+1] = k1 * c + k0 * sn;
}

// ---------------- flash-style attention: 128 q rows / block ----------------
__global__ __launch_bounds__(128)
void attn_kernel(const float* __restrict__ Q, const float* __restrict__ K,
                 const float* __restrict__ V, float* __restrict__ O)
{
    const int qt = blockIdx.x;
    const int h  = blockIdx.y;
    const int b  = blockIdx.z;
    const int stride = BATCH * DM;
    const int base   = b * DM + h * HD;
    const int t  = threadIdx.x;
    const int q0 = qt * 128;

    __shared__ float sm[2 * 64 * 65];
    float* Ks = sm;
    float* Vs = sm + 64 * 65;

    for (int i = t; i < 128 * 64; i += 128) {
        int r = i >> 6, d = i & 63;
        sm[r * 65 + d] = Q[(size_t)(q0 + r) * stride + base + d];
    }
    __syncthreads();
    float q[64];
    #pragma unroll
    for (int d = 0; d < 64; d++) q[d] = sm[t * 65 + d];
    __syncthreads();

    float o[64];
    #pragma unroll
    for (int d = 0; d < 64; d++) o[d] = 0.f;
    float m = -1e30f, l = 0.f;

    for (int kt = 0; kt < SEQ; kt += 64) {
        for (int i = t; i < 64 * 64; i += 128) {
            int r = i >> 6, d = i & 63;
            Ks[r * 65 + d] = K[(size_t)(kt + r) * stride + base + d];
            Vs[r * 65 + d] = V[(size_t)(kt + r) * stride + base + d];
        }
        __syncthreads();

        for (int j = 0; j < 64; j++) {
            float s = 0.f;
            #pragma unroll
            for (int d = 0; d < 64; d++) s += q[d] * Ks[j * 65 + d];
            s *= 0.125f;
            if (s > m) {
                float sc = __expf(m - s);
                l *= sc;
                #pragma unroll
                for (int d = 0; d < 64; d++) o[d] *= sc;
                m = s;
            }
            float p = __expf(s - m);
            l += p;
            #pragma unroll
            for (int d = 0; d < 64; d++) o[d] += p * Vs[j * 65 + d];
        }
        __syncthreads();
    }

    float inv = 1.f / l;
    #pragma unroll
    for (int d = 0; d < 64; d++)
        O[(size_t)(q0 + t) * stride + base + d] = o[d] * inv;
}

// ---------------- residual add + LayerNorm (one block per row) -------------
__global__ __launch_bounds__(256)
void add_ln_kernel(const float* __restrict__ A, const float* __restrict__ B,
                   const float* __restrict__ g, const float* __restrict__ bta,
                   float* __restrict__ out)
{
    const int row = blockIdx.x;
    const int tid = threadIdx.x;
    const float* a = A + (size_t)row * DM;
    const float* b = B + (size_t)row * DM;

    float v[4];
    float4 va = *(const float4*)(a + tid * 4);
    float4 vb = *(const float4*)(b + tid * 4);
    v[0] = va.x + vb.x; v[1] = va.y + vb.y;
    v[2] = va.z + vb.z; v[3] = va.w + vb.w;

    float sum = v[0] + v[1] + v[2] + v[3];
    float sq  = v[0]*v[0] + v[1]*v[1] + v[2]*v[2] + v[3]*v[3];

    #pragma unroll
    for (int off = 16; off; off >>= 1) {
        sum += __shfl_xor_sync(0xFFFFFFFF, sum, off);
        sq  += __shfl_xor_sync(0xFFFFFFFF, sq,  off);
    }
    __shared__ float ssum[8], ssq[8], sstat[2];
    if ((tid & 31) == 0) { ssum[tid >> 5] = sum; ssq[tid >> 5] = sq; }
    __syncthreads();
    if (tid == 0) {
        float ts = 0.f, tq = 0.f;
        #pragma unroll
        for (int i = 0; i < 8; i++) { ts += ssum[i]; tq += ssq[i]; }
        float mean = ts / (float)DM;
        float var  = tq / (float)DM - mean * mean;
        sstat[0] = mean;
        sstat[1] = rsqrtf(fmaxf(var, 0.f) + LN_EPS);
    }
    __syncthreads();
    float mean = sstat[0], inv = sstat[1];

    float4 vg = *(const float4*)(g   + tid * 4);
    float4 vB = *(const float4*)(bta + tid * 4);
    float4 r;
    r.x = (v[0] - mean) * inv * vg.x + vB.x;
    r.y = (v[1] - mean) * inv * vg.y + vB.y;
    r.z = (v[2] - mean) * inv * vg.z + vB.z;
    r.w = (v[3] - mean) * inv * vg.w + vB.w;
    *(float4*)(out + (size_t)row * DM + tid * 4) = r;
}

// ---------------------------------------------------------------------------
extern "C" void kernel_launch(void* const* d_in, const int* in_sizes, int n_in,
                              void* d_out, int out_size)
{
    const float* src  = (const float*)d_in[0];
    const float* q_w  = (const float*)d_in[1];
    const float* q_b  = (const float*)d_in[2];
    const float* k_w  = (const float*)d_in[3];
    const float* k_b  = (const float*)d_in[4];
    const float* v_w  = (const float*)d_in[5];
    const float* v_b  = (const float*)d_in[6];
    const float* w1   = (const float*)d_in[7];
    const float* b1   = (const float*)d_in[8];
    const float* w2   = (const float*)d_in[9];
    const float* b2   = (const float*)d_in[10];
    const float* ln1g = (const float*)d_in[11];
    const float* ln1b = (const float*)d_in[12];
    const float* ln2g = (const float*)d_in[13];
    const float* ln2b = (const float*)d_in[14];
    float* out = (float*)d_out;

    float *q, *k, *v, *att, *x, *ff;
    cudaGetSymbolAddress((void**)&q,   g_q);
    cudaGetSymbolAddress((void**)&k,   g_k);
    cudaGetSymbolAddress((void**)&v,   g_v);
    cudaGetSymbolAddress((void**)&att, g_att);
    cudaGetSymbolAddress((void**)&x,   g_x);
    cudaGetSymbolAddress((void**)&ff,  g_ff);

    dim3 gQKV(DM / 128, SB / 128);
    gemm_tf32<0><<<gQKV, 256>>>(src, q_w, q_b, q, SB, DM, DM);
    gemm_tf32<0><<<gQKV, 256>>>(src, k_w, k_b, k, SB, DM, DM);
    gemm_tf32<0><<<gQKV, 256>>>(src, v_w, v_b, v, SB, DM, DM);

    rope_kernel<<<(SB * DM / 2 + 255) / 256, 256>>>(q, k);

    attn_kernel<<<dim3(SEQ / 128, NH, BATCH), 128>>>(q, k, v, att);

    add_ln_kernel<<<SB, 256>>>(src, att, ln1g, ln1b, x);

    gemm_tf32<1><<<dim3(DFF / 128, SB / 128), 256>>>(x, w1, b1, ff, SB, DFF, DM);
    gemm_tf32<0><<<dim3(DM / 128, SB / 128), 256>>>(ff, w2, b2, q, SB, DM, DFF);

    add_ln_kernel<<<SB, 256>>>(x, q, ln2g, ln2b, out);
}

// round 3
// speedup vs baseline: 4.3971x; 2.9491x over previous
#include <cuda_runtime.h>
#include <cuda_bf16.h>
#include <math.h>

#define SEQ    2048
#define BATCH  2
#define DM     1024
#define NH     16
#define HD     64
#define DFF    4096
#define SB     (SEQ*BATCH)          /* 4096 rows */
#define LN_EPS 1e-5f

// ---------------- scratch (static __device__, allocation-rule safe) ---------
__device__ float g_q [SB*DM];
__device__ float g_k [SB*DM];
__device__ float g_v [SB*DM];
__device__ float g_att[SB*DM];
__device__ float g_x [SB*DM];
__device__ float g_ff[SB*DFF];

// ---------------- helpers ---------------------------------------------------
__device__ __forceinline__ unsigned f2tf32(float x) {
    unsigned r;
    asm("cvt.rna.tf32.f32 %0, %1;" : "=r"(r) : "f"(x));
    return r;
}

__device__ __forceinline__ unsigned pack_bf16x2(float lo, float hi) {
    __nv_bfloat162 h = __floats2bfloat162_rn(lo, hi);   // .x = lo, .y = hi
    return reinterpret_cast<unsigned&>(h);
}

__device__ __forceinline__ void cp16(void* smem, const void* gmem) {
    unsigned s = (unsigned)__cvta_generic_to_shared(smem);
    asm volatile("cp.async.cg.shared.global [%0], [%1], 16;" :: "r"(s), "l"(gmem));
}

__device__ __forceinline__ void mma_tf32(float c[4],
                                         unsigned a0, unsigned a1, unsigned a2, unsigned a3,
                                         unsigned b0, unsigned b1) {
    asm volatile(
        "mma.sync.aligned.m16n8k8.row.col.f32.tf32.tf32.f32 "
        "{%0,%1,%2,%3}, {%4,%5,%6,%7}, {%8,%9}, {%0,%1,%2,%3};"
        : "+f"(c[0]), "+f"(c[1]), "+f"(c[2]), "+f"(c[3])
        : "r"(a0), "r"(a1), "r"(a2), "r"(a3), "r"(b0), "r"(b1));
}

__device__ __forceinline__ void mma_bf16(float c[4],
                                         unsigned a0, unsigned a1, unsigned a2, unsigned a3,
                                         unsigned b0, unsigned b1) {
    asm volatile(
        "mma.sync.aligned.m16n8k16.row.col.f32.bf16.bf16.f32 "
        "{%0,%1,%2,%3}, {%4,%5,%6,%7}, {%8,%9}, {%0,%1,%2,%3};"
        : "+f"(c[0]), "+f"(c[1]), "+f"(c[2]), "+f"(c[3])
        : "r"(a0), "r"(a1), "r"(a2), "r"(a3), "r"(b0), "r"(b1));
}

// ---------------- TF32 tensor-core GEMM: C = A@B + bias (opt relu) ----------
template<int RELU>
__global__ __launch_bounds__(256, 2)
void gemm_tf32(const float* __restrict__ A, const float* __restrict__ B,
               const float* __restrict__ bias, float* __restrict__ C,
               int M, int N, int K)
{
    __shared__ float As[2][128][20];
    __shared__ float Bs[2][16][136];

    const int tid  = threadIdx.x;
    const int warp = tid >> 5, lane = tid & 31;
    const int g = lane >> 2, t = lane & 3;
    const int wm = warp >> 1, wn = warp & 1;
    const int bm = blockIdx.y * 128, bn = blockIdx.x * 128;

    float acc[2][8][4];
    #pragma unroll
    for (int i = 0; i < 2; i++)
        #pragma unroll
        for (int j = 0; j < 8; j++)
            #pragma unroll
            for (int r = 0; r < 4; r++) acc[i][j][r] = 0.f;

    const int KT = K / 16;

    auto load_stage = [&](int s, int kt) {
        #pragma unroll
        for (int u = 0; u < 2; u++) {
            int f  = tid + u * 256;
            int ar = f >> 2, ak = (f & 3) * 4;
            cp16(&As[s][ar][ak], A + (size_t)(bm + ar) * K + kt + ak);
            int br = f >> 5, bc = (f & 31) * 4;
            cp16(&Bs[s][br][bc], B + (size_t)(kt + br) * N + bn + bc);
        }
        asm volatile("cp.async.commit_group;");
    };

    load_stage(0, 0);

    for (int kt = 0; kt < KT; kt++) {
        if (kt + 1 < KT) {
            load_stage((kt + 1) & 1, (kt + 1) * 16);
            asm volatile("cp.async.wait_group 1;");
        } else {
            asm volatile("cp.async.wait_group 0;");
        }
        __syncthreads();

        const int s = kt & 1;
        #pragma unroll
        for (int ks = 0; ks < 2; ks++) {
            const int k0 = ks * 8;
            unsigned a[2][4];
            #pragma unroll
            for (int mf = 0; mf < 2; mf++) {
                int m = wm * 32 + mf * 16 + g;
                a[mf][0] = f2tf32(As[s][m    ][k0 + t    ]);
                a[mf][1] = f2tf32(As[s][m + 8][k0 + t    ]);
                a[mf][2] = f2tf32(As[s][m    ][k0 + t + 4]);
                a[mf][3] = f2tf32(As[s][m + 8][k0 + t + 4]);
            }
            #pragma unroll
            for (int nf = 0; nf < 8; nf++) {
                int n = wn * 64 + nf * 8 + g;
                unsigned b0 = f2tf32(Bs[s][k0 + t    ][n]);
                unsigned b1 = f2tf32(Bs[s][k0 + t + 4][n]);
                mma_tf32(acc[0][nf], a[0][0], a[0][1], a[0][2], a[0][3], b0, b1);
                mma_tf32(acc[1][nf], a[1][0], a[1][1], a[1][2], a[1][3], b0, b1);
            }
        }
        __syncthreads();
    }

    #pragma unroll
    for (int mf = 0; mf < 2; mf++) {
        int r0 = bm + wm * 32 + mf * 16 + g;
        #pragma unroll
        for (int nf = 0; nf < 8; nf++) {
            int col = bn + wn * 64 + nf * 8 + t * 2;
            float2 bv = *(const float2*)(bias + col);
            float2 v0, v1;
            v0.x = acc[mf][nf][0] + bv.x; v0.y = acc[mf][nf][1] + bv.y;
            v1.x = acc[mf][nf][2] + bv.x; v1.y = acc[mf][nf][3] + bv.y;
            if (RELU) {
                v0.x = fmaxf(v0.x, 0.f); v0.y = fmaxf(v0.y, 0.f);
                v1.x = fmaxf(v1.x, 0.f); v1.y = fmaxf(v1.y, 0.f);
            }
            *(float2*)(C + (size_t)r0       * N + col) = v0;
            *(float2*)(C + (size_t)(r0 + 8) * N + col) = v1;
        }
    }
}

// ---------------- RoPE (interleaved pairs), applied in-place to Q and K -----
__global__ void rope_kernel(float* __restrict__ Q, float* __restrict__ K)
{
    int idx = blockIdx.x * blockDim.x + threadIdx.x;
    if (idx >= SB * DM / 2) return;
    int flat = idx * 2;
    int d    = flat % HD;
    int s    = flat / (BATCH * DM);

    float angle = (float)s * powf(10000.0f, -(float)d / (float)HD);
    float c = cosf(angle), sn = sinf(angle);

    float q0 = Q[flat], q1 = Q[flat+1];
    Q[flat]   = q0 * c - q1 * sn;
    Q[flat+1] = q1 * c + q0 * sn;
    float k0 = K[flat], k1 = K[flat+1];
    K[flat]   = k0 * c - k1 * sn;
    K[flat+1] = k1 * c + k0 * sn;
}

// ---------------- tensor-core flash attention -------------------------------
// Grid (SEQ/128, NH, BATCH), 256 thr = 8 warps. Warp owns 16 q-rows.
// QK^T: tf32 m16n8k8 (Q frags in regs). softmax online. P@V: bf16 m16n8k16,
// S-accum C-layout == bf16 A-layout (FA2 trick, no permutation needed).
__global__ __launch_bounds__(256)
void attn_mma(const float* __restrict__ Q, const float* __restrict__ K,
              const float* __restrict__ V, float* __restrict__ O)
{
    const int qt = blockIdx.x, h = blockIdx.y, b = blockIdx.z;
    const int stride = BATCH * DM;
    const size_t base = (size_t)b * DM + h * HD;
    const int tid = threadIdx.x;
    const int w = tid >> 5, lane = tid & 31;
    const int g = lane >> 2, t = lane & 3;
    const int qrow0 = qt * 128 + w * 16 + g;

    __shared__ float    Ks[64][68];   // [kv][hd], LDS bank = 4g+t (conflict-free)
    __shared__ unsigned Vs[32][72];   // bf16x2 pairs along kv; bank = 8t+g

    // Q fragments (tf32), loaded once: 8 k-steps x 4 regs
    unsigned qf[8][4];
    {
        const float* Qr0 = Q + (size_t)qrow0 * stride + base;
        const float* Qr1 = Qr0 + (size_t)8 * stride;
        #pragma unroll
        for (int c = 0; c < 8; c++) {
            qf[c][0] = f2tf32(Qr0[c*8 + t]);
            qf[c][1] = f2tf32(Qr1[c*8 + t]);
            qf[c][2] = f2tf32(Qr0[c*8 + t + 4]);
            qf[c][3] = f2tf32(Qr1[c*8 + t + 4]);
        }
    }

    float oacc[8][4];
    #pragma unroll
    for (int n = 0; n < 8; n++)
        #pragma unroll
        for (int r = 0; r < 4; r++) oacc[n][r] = 0.f;
    float m0 = -1e30f, m1 = -1e30f, l0 = 0.f, l1 = 0.f;

    for (int kt = 0; kt < SEQ; kt += 64) {
        __syncthreads();
        // K tile: 64x64 floats (1024 float4)
        for (int i = tid; i < 1024; i += 256) {
            int r = i >> 4, d4 = (i & 15) * 4;
            *(float4*)&Ks[r][d4] =
                *(const float4*)(K + (size_t)(kt + r) * stride + base + d4);
        }
        // V tile: bf16x2 pairs (kv 2kp, 2kp+1) per hd col
        for (int i = tid; i < 2048; i += 256) {
            int kp = i >> 6, d = i & 63;
            float v0 = V[(size_t)(kt + 2*kp    ) * stride + base + d];
            float v1 = V[(size_t)(kt + 2*kp + 1) * stride + base + d];
            Vs[kp][d] = pack_bf16x2(v0, v1);
        }
        __syncthreads();

        // ---- S = Q @ K^T (tf32) ----
        float sacc[8][4];
        #pragma unroll
        for (int n = 0; n < 8; n++)
            #pragma unroll
            for (int r = 0; r < 4; r++) sacc[n][r] = 0.f;

        #pragma unroll
        for (int c = 0; c < 8; c++) {
            #pragma unroll
            for (int n = 0; n < 8; n++) {
                unsigned b0 = f2tf32(Ks[n*8 + g][c*8 + t    ]);
                unsigned b1 = f2tf32(Ks[n*8 + g][c*8 + t + 4]);
                mma_tf32(sacc[n], qf[c][0], qf[c][1], qf[c][2], qf[c][3], b0, b1);
            }
        }

        // ---- online softmax ----
        float mx0 = -1e30f, mx1 = -1e30f;
        #pragma unroll
        for (int n = 0; n < 8; n++) {
            sacc[n][0] *= 0.125f; sacc[n][1] *= 0.125f;
            sacc[n][2] *= 0.125f; sacc[n][3] *= 0.125f;
            mx0 = fmaxf(mx0, fmaxf(sacc[n][0], sacc[n][1]));
            mx1 = fmaxf(mx1, fmaxf(sacc[n][2], sacc[n][3]));
        }
        mx0 = fmaxf(mx0, __shfl_xor_sync(0xFFFFFFFFu, mx0, 1));
        mx0 = fmaxf(mx0, __shfl_xor_sync(0xFFFFFFFFu, mx0, 2));
        mx1 = fmaxf(mx1, __shfl_xor_sync(0xFFFFFFFFu, mx1, 1));
        mx1 = fmaxf(mx1, __shfl_xor_sync(0xFFFFFFFFu, mx1, 2));

        float nm0 = fmaxf(m0, mx0), nm1 = fmaxf(m1, mx1);
        float sc0 = __expf(m0 - nm0), sc1 = __expf(m1 - nm1);
        m0 = nm0; m1 = nm1;

        float rs0 = 0.f, rs1 = 0.f;
        unsigned pa[4][4];                      // bf16 A-frags for P@V
        #pragma unroll
        for (int n = 0; n < 8; n++) {
            float p0 = __expf(sacc[n][0] - nm0);
            float p1 = __expf(sacc[n][1] - nm0);
            float p2 = __expf(sacc[n][2] - nm1);
            float p3 = __expf(sacc[n][3] - nm1);
            rs0 += p0 + p1; rs1 += p2 + p3;
            int kk = n >> 1, half = n & 1;
            pa[kk][half*2 + 0] = pack_bf16x2(p0, p1);   // row g
            pa[kk][half*2 + 1] = pack_bf16x2(p2, p3);   // row g+8
        }
        rs0 += __shfl_xor_sync(0xFFFFFFFFu, rs0, 1);
        rs0 += __shfl_xor_sync(0xFFFFFFFFu, rs0, 2);
        rs1 += __shfl_xor_sync(0xFFFFFFFFu, rs1, 1);
        rs1 += __shfl_xor_sync(0xFFFFFFFFu, rs1, 2);
        l0 = l0 * sc0 + rs0;
        l1 = l1 * sc1 + rs1;

        #pragma unroll
        for (int n = 0; n < 8; n++) {
            oacc[n][0] *= sc0; oacc[n][1] *= sc0;
            oacc[n][2] *= sc1; oacc[n][3] *= sc1;
        }

        // ---- O += P @ V (bf16) ----
        #pragma unroll
        for (int kk = 0; kk < 4; kk++) {
            #pragma unroll
            for (int nn = 0; nn < 8; nn++) {
                unsigned b0 = Vs[kk*8 + t    ][nn*8 + g];
                unsigned b1 = Vs[kk*8 + t + 4][nn*8 + g];
                mma_bf16(oacc[nn], pa[kk][0], pa[kk][1], pa[kk][2], pa[kk][3], b0, b1);
            }
        }
    }

    float inv0 = 1.f / l0, inv1 = 1.f / l1;
    float* Or0 = O + (size_t)qrow0 * stride + base;
    float* Or1 = Or0 + (size_t)8 * stride;
    #pragma unroll
    for (int nn = 0; nn < 8; nn++) {
        float2 v0 = { oacc[nn][0] * inv0, oacc[nn][1] * inv0 };
        float2 v1 = { oacc[nn][2] * inv1, oacc[nn][3] * inv1 };
        *(float2*)(Or0 + nn*8 + 2*t) = v0;
        *(float2*)(Or1 + nn*8 + 2*t) = v1;
    }
}

// ---------------- residual add + LayerNorm (one block per row) -------------
__global__ __launch_bounds__(256)
void add_ln_kernel(const float* __restrict__ A, const float* __restrict__ B,
                   const float* __restrict__ g, const float* __restrict__ bta,
                   float* __restrict__ out)
{
    const int row = blockIdx.x;
    const int tid = threadIdx.x;
    const float* a = A + (size_t)row * DM;
    const float* b = B + (size_t)row * DM;

    float v[4];
    float4 va = *(const float4*)(a + tid * 4);
    float4 vb = *(const float4*)(b + tid * 4);
    v[0] = va.x + vb.x; v[1] = va.y + vb.y;
    v[2] = va.z + vb.z; v[3] = va.w + vb.w;

    float sum = v[0] + v[1] + v[2] + v[3];
    float sq  = v[0]*v[0] + v[1]*v[1] + v[2]*v[2] + v[3]*v[3];

    #pragma unroll
    for (int off = 16; off; off >>= 1) {
        sum += __shfl_xor_sync(0xFFFFFFFF, sum, off);
        sq  += __shfl_xor_sync(0xFFFFFFFF, sq,  off);
    }
    __shared__ float ssum[8], ssq[8], sstat[2];
    if ((tid & 31) == 0) { ssum[tid >> 5] = sum; ssq[tid >> 5] = sq; }
    __syncthreads();
    if (tid == 0) {
        float ts = 0.f, tq = 0.f;
        #pragma unroll
        for (int i = 0; i < 8; i++) { ts += ssum[i]; tq += ssq[i]; }
        float mean = ts / (float)DM;
        float var  = tq / (float)DM - mean * mean;
        sstat[0] = mean;
        sstat[1] = rsqrtf(fmaxf(var, 0.f) + LN_EPS);
    }
    __syncthreads();
    float mean = sstat[0], inv = sstat[1];

    float4 vg = *(const float4*)(g   + tid * 4);
    float4 vB = *(const float4*)(bta + tid * 4);
    float4 r;
    r.x = (v[0] - mean) * inv * vg.x + vB.x;
    r.y = (v[1] - mean) * inv * vg.y + vB.y;
    r.z = (v[2] - mean) * inv * vg.z + vB.z;
    r.w = (v[3] - mean) * inv * vg.w + vB.w;
    *(float4*)(out + (size_t)row * DM + tid * 4) = r;
}

// ---------------------------------------------------------------------------
extern "C" void kernel_launch(void* const* d_in, const int* in_sizes, int n_in,
                              void* d_out, int out_size)
{
    const float* src  = (const float*)d_in[0];
    const float* q_w  = (const float*)d_in[1];
    const float* q_b  = (const float*)d_in[2];
    const float* k_w  = (const float*)d_in[3];
    const float* k_b  = (const float*)d_in[4];
    const float* v_w  = (const float*)d_in[5];
    const float* v_b  = (const float*)d_in[6];
    const float* w1   = (const float*)d_in[7];
    const float* b1   = (const float*)d_in[8];
    const float* w2   = (const float*)d_in[9];
    const float* b2   = (const float*)d_in[10];
    const float* ln1g = (const float*)d_in[11];
    const float* ln1b = (const float*)d_in[12];
    const float* ln2g = (const float*)d_in[13];
    const float* ln2b = (const float*)d_in[14];
    float* out = (float*)d_out;

    float *q, *k, *v, *att, *x, *ff;
    cudaGetSymbolAddress((void**)&q,   g_q);
    cudaGetSymbolAddress((void**)&k,   g_k);
    cudaGetSymbolAddress((void**)&v,   g_v);
    cudaGetSymbolAddress((void**)&att, g_att);
    cudaGetSymbolAddress((void**)&x,   g_x);
    cudaGetSymbolAddress((void**)&ff,  g_ff);

    dim3 gQKV(DM / 128, SB / 128);
    gemm_tf32<0><<<gQKV, 256>>>(src, q_w, q_b, q, SB, DM, DM);
    gemm_tf32<0><<<gQKV, 256>>>(src, k_w, k_b, k, SB, DM, DM);
    gemm_tf32<0><<<gQKV, 256>>>(src, v_w, v_b, v, SB, DM, DM);

    rope_kernel<<<(SB * DM / 2 + 255) / 256, 256>>>(q, k);

    attn_mma<<<dim3(SEQ / 128, NH, BATCH), 256>>>(q, k, v, att);

    add_ln_kernel<<<SB, 256>>>(src, att, ln1g, ln1b, x);

    gemm_tf32<1><<<dim3(DFF / 128, SB / 128), 256>>>(x, w1, b1, ff, SB, DFF, DM);
    gemm_tf32<0><<<dim3(DM / 128, SB / 128), 256>>>(ff, w2, b2, q, SB, DM, DFF);

    add_ln_kernel<<<SB, 256>>>(x, q, ln2g, ln2b, out);
}

// round 5
// speedup vs baseline: 6.8989x; 1.5690x over previous
#include <cuda_runtime.h>
#include <cuda_fp16.h>
#include <math.h>
#include <stdint.h>

#define SEQ    2048
#define BATCH  2
#define DM     1024
#define NH     16
#define HD     64
#define DFF    4096
#define SB     (SEQ*BATCH)          /* 4096 rows */
#define LN_EPS 1e-5f

// ---------------- scratch (static __device__, allocation-rule safe) ---------
__device__ float g_q [SB*DM];
__device__ float g_k [SB*DM];
__device__ float g_v [SB*DM];
__device__ float g_att[SB*DM];
__device__ float g_x [SB*DM];

__device__ __half g_srch[SB*DM];
__device__ __half g_xh  [SB*DM];
__device__ __half g_ffh [SB*DFF];
__device__ __half g_wqt [DM*DM];
__device__ __half g_wkt [DM*DM];
__device__ __half g_wvt [DM*DM];
__device__ __half g_w1t [DFF*DM];
__device__ __half g_w2t [DM*DFF];

// ---------------- helpers ---------------------------------------------------
__device__ __forceinline__ unsigned pack_half2(float lo, float hi) {
    __half2 h = __floats2half2_rn(lo, hi);     // .x = lo (low 16 bits)
    return reinterpret_cast<unsigned&>(h);
}
__device__ __forceinline__ void cp16(unsigned dst, const void* gmem) {
    asm volatile("cp.async.cg.shared.global [%0], [%1], 16;" :: "r"(dst), "l"(gmem));
}
__device__ __forceinline__ unsigned smem_u32(const void* p) {
    return (unsigned)__cvta_generic_to_shared(p);
}
__device__ __forceinline__ void mma_fp16(float c[4],
                                         unsigned a0, unsigned a1, unsigned a2, unsigned a3,
                                         unsigned b0, unsigned b1) {
    asm volatile(
        "mma.sync.aligned.m16n8k16.row.col.f32.f16.f16.f32 "
        "{%0,%1,%2,%3}, {%4,%5,%6,%7}, {%8,%9}, {%0,%1,%2,%3};"
        : "+f"(c[0]), "+f"(c[1]), "+f"(c[2]), "+f"(c[3])
        : "r"(a0), "r"(a1), "r"(a2), "r"(a3), "r"(b0), "r"(b1));
}

// ---------------- fp16 tensor-core GEMM: C = A@Bt^T + bias ------------------
// A: [M,K] fp16 row-major. Bt: [N,K] fp16 row-major (pre-transposed weight).
// Tile 128x128, BK=32, 8 warps (4x2), warp tile 32x64, 2-stage cp.async.
// smem rows are u32 (fp16 pairs along K), stride 20 u32 -> conflict-free frags.
template<int RELU, int HALF_OUT>
__global__ __launch_bounds__(256, 2)
void gemm_fp16(const __half* __restrict__ A, const __half* __restrict__ Bt,
               const float* __restrict__ bias,
               float* __restrict__ Cf, __half* __restrict__ Ch,
               int M, int N, int K)
{
    __shared__ unsigned As[2][128][20];
    __shared__ unsigned Bs[2][128][20];

    const int tid  = threadIdx.x;
    const int warp = tid >> 5, lane = tid & 31;
    const int g = lane >> 2, t = lane & 3;
    const int wm = warp >> 1, wn = warp & 1;
    const int bm = blockIdx.y * 128, bn = blockIdx.x * 128;

    float acc[2][8][4];
    #pragma unroll
    for (int i = 0; i < 2; i++)
        #pragma unroll
        for (int j = 0; j < 8; j++)
            #pragma unroll
            for (int r = 0; r < 4; r++) acc[i][j][r] = 0.f;

    const int NC = K >> 5;          // chunks of 32

    auto load_stage = [&](int s, int kt) {
        #pragma unroll
        for (int u = 0; u < 2; u++) {
            int f = tid + u * 256;                 // 0..511
            int r = f >> 2, j = f & 3;             // row, 16B chunk (8 fp16)
            cp16(smem_u32(&As[s][r][j * 4]), A  + (size_t)(bm + r) * K + kt + j * 8);
            cp16(smem_u32(&Bs[s][r][j * 4]), Bt + (size_t)(bn + r) * K + kt + j * 8);
        }
        asm volatile("cp.async.commit_group;");
    };

    load_stage(0, 0);

    for (int c = 0; c < NC; c++) {
        if (c + 1 < NC) {
            load_stage((c + 1) & 1, (c + 1) * 32);
            asm volatile("cp.async.wait_group 1;");
        } else {
            asm volatile("cp.async.wait_group 0;");
        }
        __syncthreads();

        const int s = c & 1;
        #pragma unroll
        for (int ks = 0; ks < 2; ks++) {
            const int kp = ks * 8;                 // pair base (k16 step)
            unsigned a[2][4];
            #pragma unroll
            for (int mf = 0; mf < 2; mf++) {
                int m = wm * 32 + mf * 16 + g;
                a[mf][0] = As[s][m    ][kp + t    ];
                a[mf][1] = As[s][m + 8][kp + t    ];
                a[mf][2] = As[s][m    ][kp + t + 4];
                a[mf][3] = As[s][m + 8][kp + t + 4];
            }
            #pragma unroll
            for (int nf = 0; nf < 8; nf++) {
                int n = wn * 64 + nf * 8 + g;
                unsigned b0 = Bs[s][n][kp + t    ];
                unsigned b1 = Bs[s][n][kp + t + 4];
                mma_fp16(acc[0][nf], a[0][0], a[0][1], a[0][2], a[0][3], b0, b1);
                mma_fp16(acc[1][nf], a[1][0], a[1][1], a[1][2], a[1][3], b0, b1);
            }
        }
        __syncthreads();
    }

    // epilogue: C frag rows (g, g+8), cols (2t, 2t+1)
    #pragma unroll
    for (int mf = 0; mf < 2; mf++) {
        int r0 = bm + wm * 32 + mf * 16 + g;
        #pragma unroll
        for (int nf = 0; nf < 8; nf++) {
            int col = bn + wn * 64 + nf * 8 + 2 * t;
            float2 bv = *(const float2*)(bias + col);
            float v0 = acc[mf][nf][0] + bv.x;
            float v1 = acc[mf][nf][1] + bv.y;
            float v2 = acc[mf][nf][2] + bv.x;
            float v3 = acc[mf][nf][3] + bv.y;
            if (RELU) {
                v0 = fmaxf(v0, 0.f); v1 = fmaxf(v1, 0.f);
                v2 = fmaxf(v2, 0.f); v3 = fmaxf(v3, 0.f);
            }
            if (HALF_OUT) {
                *(__half2*)(Ch + (size_t)r0       * N + col) = __floats2half2_rn(v0, v1);
                *(__half2*)(Ch + (size_t)(r0 + 8) * N + col) = __floats2half2_rn(v2, v3);
            } else {
                *(float2*)(Cf + (size_t)r0       * N + col) = make_float2(v0, v1);
                *(float2*)(Cf + (size_t)(r0 + 8) * N + col) = make_float2(v2, v3);
            }
        }
    }
}

// ---------------- pre-pass: f32 -> fp16 copy --------------------------------
__global__ void to_half(const float* __restrict__ X, __half* __restrict__ H, int n4)
{
    int i = blockIdx.x * blockDim.x + threadIdx.x;
    if (i >= n4) return;
    float4 v = *(const float4*)(X + i * 4);
    *(__half2*)(H + i * 4)     = __floats2half2_rn(v.x, v.y);
    *(__half2*)(H + i * 4 + 2) = __floats2half2_rn(v.z, v.w);
}

// ---------------- pre-pass: W[K,N] -> Wt[N,K] fp16 --------------------------
__global__ void transpose_half(const float* __restrict__ W, __half* __restrict__ T,
                               int K, int N)
{
    __shared__ float tl[32][33];
    int n0 = blockIdx.x * 32, k0 = blockIdx.y * 32;
    int x = threadIdx.x, y = threadIdx.y;
    #pragma unroll
    for (int i = 0; i < 4; i++) {
        int r = y + i * 8;
        tl[r][x] = W[(size_t)(k0 + r) * N + n0 + x];
    }
    __syncthreads();
    #pragma unroll
    for (int i = 0; i < 4; i++) {
        int r = y + i * 8;
        T[(size_t)(n0 + r) * K + k0 + x] = __float2half_rn(tl[x][r]);
    }
}

// ---------------- RoPE (interleaved pairs), in-place on Q and K -------------
__global__ void rope_kernel(float* __restrict__ Q, float* __restrict__ K)
{
    int idx = blockIdx.x * blockDim.x + threadIdx.x;
    if (idx >= SB * DM / 2) return;
    int flat = idx * 2;
    int d    = flat % HD;
    int s    = flat / (BATCH * DM);

    float angle = (float)s * powf(10000.0f, -(float)d / (float)HD);
    float c = cosf(angle), sn = sinf(angle);

    float q0 = Q[flat], q1 = Q[flat+1];
    Q[flat]   = q0 * c - q1 * sn;
    Q[flat+1] = q1 * c + q0 * sn;
    float k0 = K[flat], k1 = K[flat+1];
    K[flat]   = k0 * c - k1 * sn;
    K[flat+1] = k1 * c + k0 * sn;
}

// ---------------- tensor-core flash attention (fp16 mma) --------------------
// Grid (SEQ/128, NH, BATCH), 256 thr = 8 warps. Warp owns 16 q-rows.
__global__ __launch_bounds__(256)
void attn_mma(const float* __restrict__ Q, const float* __restrict__ K,
              const float* __restrict__ V, float* __restrict__ O)
{
    const int qt = blockIdx.x, h = blockIdx.y, b = blockIdx.z;
    const int stride = BATCH * DM;
    const size_t base = (size_t)b * DM + h * HD;
    const int tid = threadIdx.x;
    const int w = tid >> 5, lane = tid & 31;
    const int g = lane >> 2, t = lane & 3;
    const int qrow0 = qt * 128 + w * 16 + g;

    __shared__ unsigned Ks[64][36];   // fp16 pairs along hd; banks (4g+t) free
    __shared__ unsigned Vs[32][72];   // fp16 pairs along kv; banks (8t+g) free

    // Q fragments (fp16): 4 k16-steps x 4 regs
    unsigned qf[4][4];
    {
        const float* Qr0 = Q + (size_t)qrow0 * stride + base;
        const float* Qr1 = Qr0 + (size_t)8 * stride;
        #pragma unroll
        for (int c = 0; c < 4; c++) {
            float2 x0 = *(const float2*)(Qr0 + 16*c + 2*t);
            float2 x1 = *(const float2*)(Qr1 + 16*c + 2*t);
            float2 x2 = *(const float2*)(Qr0 + 16*c + 8 + 2*t);
            float2 x3 = *(const float2*)(Qr1 + 16*c + 8 + 2*t);
            qf[c][0] = pack_half2(x0.x, x0.y);
            qf[c][1] = pack_half2(x1.x, x1.y);
            qf[c][2] = pack_half2(x2.x, x2.y);
            qf[c][3] = pack_half2(x3.x, x3.y);
        }
    }

    float oacc[8][4];
    #pragma unroll
    for (int n = 0; n < 8; n++)
        #pragma unroll
        for (int r = 0; r < 4; r++) oacc[n][r] = 0.f;
    float m0 = -1e30f, m1 = -1e30f, l0 = 0.f, l1 = 0.f;

    for (int kt = 0; kt < SEQ; kt += 64) {
        __syncthreads();
        // K tile: 64 kv x 32 hd-pairs
        for (int i = tid; i < 2048; i += 256) {
            int r = i >> 5, dp = i & 31;
            float2 kv = *(const float2*)(K + (size_t)(kt + r) * stride + base + 2*dp);
            Ks[r][dp] = pack_half2(kv.x, kv.y);
        }
        // V tile: pairs along kv
        for (int i = tid; i < 2048; i += 256) {
            int kp = i >> 6, d = i & 63;
            float v0 = V[(size_t)(kt + 2*kp    ) * stride + base + d];
            float v1 = V[(size_t)(kt + 2*kp + 1) * stride + base + d];
            Vs[kp][d] = pack_half2(v0, v1);
        }
        __syncthreads();

        // ---- S = Q @ K^T (fp16) ----
        float sacc[8][4];
        #pragma unroll
        for (int n = 0; n < 8; n++)
            #pragma unroll
            for (int r = 0; r < 4; r++) sacc[n][r] = 0.f;

        #pragma unroll
        for (int c = 0; c < 4; c++) {
            #pragma unroll
            for (int n = 0; n < 8; n++) {
                unsigned b0 = Ks[n*8 + g][c*8 + t    ];
                unsigned b1 = Ks[n*8 + g][c*8 + t + 4];
                mma_fp16(sacc[n], qf[c][0], qf[c][1], qf[c][2], qf[c][3], b0, b1);
            }
        }

        // ---- online softmax ----
        float mx0 = -1e30f, mx1 = -1e30f;
        #pragma unroll
        for (int n = 0; n < 8; n++) {
            sacc[n][0] *= 0.125f; sacc[n][1] *= 0.125f;
            sacc[n][2] *= 0.125f; sacc[n][3] *= 0.125f;
            mx0 = fmaxf(mx0, fmaxf(sacc[n][0], sacc[n][1]));
            mx1 = fmaxf(mx1, fmaxf(sacc[n][2], sacc[n][3]));
        }
        mx0 = fmaxf(mx0, __shfl_xor_sync(0xFFFFFFFFu, mx0, 1));
        mx0 = fmaxf(mx0, __shfl_xor_sync(0xFFFFFFFFu, mx0, 2));
        mx1 = fmaxf(mx1, __shfl_xor_sync(0xFFFFFFFFu, mx1, 1));
        mx1 = fmaxf(mx1, __shfl_xor_sync(0xFFFFFFFFu, mx1, 2));

        float nm0 = fmaxf(m0, mx0), nm1 = fmaxf(m1, mx1);
        float sc0 = __expf(m0 - nm0), sc1 = __expf(m1 - nm1);
        m0 = nm0; m1 = nm1;

        float rs0 = 0.f, rs1 = 0.f;
        unsigned pa[4][4];
        #pragma unroll
        for (int n = 0; n < 8; n++) {
            float p0 = __expf(sacc[n][0] - nm0);
            float p1 = __expf(sacc[n][1] - nm0);
            float p2 = __expf(sacc[n][2] - nm1);
            float p3 = __expf(sacc[n][3] - nm1);
            rs0 += p0 + p1; rs1 += p2 + p3;
            int kk = n >> 1, half = n & 1;
            pa[kk][half*2 + 0] = pack_half2(p0, p1);   // row g
            pa[kk][half*2 + 1] = pack_half2(p2, p3);   // row g+8
        }
        rs0 += __shfl_xor_sync(0xFFFFFFFFu, rs0, 1);
        rs0 += __shfl_xor_sync(0xFFFFFFFFu, rs0, 2);
        rs1 += __shfl_xor_sync(0xFFFFFFFFu, rs1, 1);
        rs1 += __shfl_xor_sync(0xFFFFFFFFu, rs1, 2);
        l0 = l0 * sc0 + rs0;
        l1 = l1 * sc1 + rs1;

        #pragma unroll
        for (int n = 0; n < 8; n++) {
            oacc[n][0] *= sc0; oacc[n][1] *= sc0;
            oacc[n][2] *= sc1; oacc[n][3] *= sc1;
        }

        // ---- O += P @ V (fp16) ----
        #pragma unroll
        for (int kk = 0; kk < 4; kk++) {
            #pragma unroll
            for (int nn = 0; nn < 8; nn++) {
                unsigned b0 = Vs[kk*8 + t    ][nn*8 + g];
                unsigned b1 = Vs[kk*8 + t + 4][nn*8 + g];
                mma_fp16(oacc[nn], pa[kk][0], pa[kk][1], pa[kk][2], pa[kk][3], b0, b1);
            }
        }
    }

    float inv0 = 1.f / l0, inv1 = 1.f / l1;
    float* Or0 = O + (size_t)qrow0 * stride + base;
    float* Or1 = Or0 + (size_t)8 * stride;
    #pragma unroll
    for (int nn = 0; nn < 8; nn++) {
        float2 v0 = { oacc[nn][0] * inv0, oacc[nn][1] * inv0 };
        float2 v1 = { oacc[nn][2] * inv1, oacc[nn][3] * inv1 };
        *(float2*)(Or0 + nn*8 + 2*t) = v0;
        *(float2*)(Or1 + nn*8 + 2*t) = v1;
    }
}

// ---------------- residual add + LayerNorm (+ optional fp16 copy out) -------
template<int HALF>
__global__ __launch_bounds__(256)
void add_ln_kernel(const float* __restrict__ A, const float* __restrict__ B,
                   const float* __restrict__ g, const float* __restrict__ bta,
                   float* __restrict__ out, __half* __restrict__ oh)
{
    const int row = blockIdx.x;
    const int tid = threadIdx.x;
    const float* a = A + (size_t)row * DM;
    const float* b = B + (size_t)row * DM;

    float v[4];
    float4 va = *(const float4*)(a + tid * 4);
    float4 vb = *(const float4*)(b + tid * 4);
    v[0] = va.x + vb.x; v[1] = va.y + vb.y;
    v[2] = va.z + vb.z; v[3] = va.w + vb.w;

    float sum = v[0] + v[1] + v[2] + v[3];
    float sq  = v[0]*v[0] + v[1]*v[1] + v[2]*v[2] + v[3]*v[3];

    #pragma unroll
    for (int off = 16; off; off >>= 1) {
        sum += __shfl_xor_sync(0xFFFFFFFF, sum, off);
        sq  += __shfl_xor_sync(0xFFFFFFFF, sq,  off);
    }
    __shared__ float ssum[8], ssq[8], sstat[2];
    if ((tid & 31) == 0) { ssum[tid >> 5] = sum; ssq[tid >> 5] = sq; }
    __syncthreads();
    if (tid == 0) {
        float ts = 0.f, tq = 0.f;
        #pragma unroll
        for (int i = 0; i < 8; i++) { ts += ssum[i]; tq += ssq[i]; }
        float mean = ts / (float)DM;
        float var  = tq / (float)DM - mean * mean;
        sstat[0] = mean;
        sstat[1] = rsqrtf(fmaxf(var, 0.f) + LN_EPS);
    }
    __syncthreads();
    float mean = sstat[0], inv = sstat[1];

    float4 vg = *(const float4*)(g   + tid * 4);
    float4 vB = *(const float4*)(bta + tid * 4);
    float4 r;
    r.x = (v[0] - mean) * inv * vg.x + vB.x;
    r.y = (v[1] - mean) * inv * vg.y + vB.y;
    r.z = (v[2] - mean) * inv * vg.z + vB.z;
    r.w = (v[3] - mean) * inv * vg.w + vB.w;
    *(float4*)(out + (size_t)row * DM + tid * 4) = r;

    if (HALF) {
        *(__half2*)(oh + (size_t)row * DM + tid * 4)     = __floats2half2_rn(r.x, r.y);
        *(__half2*)(oh + (size_t)row * DM + tid * 4 + 2) = __floats2half2_rn(r.z, r.w);
    }
}

// ---------------------------------------------------------------------------
extern "C" void kernel_launch(void* const* d_in, const int* in_sizes, int n_in,
                              void* d_out, int out_size)
{
    const float* src  = (const float*)d_in[0];
    const float* q_w  = (const float*)d_in[1];
    const float* q_b  = (const float*)d_in[2];
    const float* k_w  = (const float*)d_in[3];
    const float* k_b  = (const float*)d_in[4];
    const float* v_w  = (const float*)d_in[5];
    const float* v_b  = (const float*)d_in[6];
    const float* w1   = (const float*)d_in[7];
    const float* b1   = (const float*)d_in[8];
    const float* w2   = (const float*)d_in[9];
    const float* b2   = (const float*)d_in[10];
    const float* ln1g = (const float*)d_in[11];
    const float* ln1b = (const float*)d_in[12];
    const float* ln2g = (const float*)d_in[13];
    const float* ln2b = (const float*)d_in[14];
    float* out = (float*)d_out;

    float *q, *k, *v, *att, *x;
    __half *sh, *xh, *ffh, *wqt, *wkt, *wvt, *w1t, *w2t;
    cudaGetSymbolAddress((void**)&q,   g_q);
    cudaGetSymbolAddress((void**)&k,   g_k);
    cudaGetSymbolAddress((void**)&v,   g_v);
    cudaGetSymbolAddress((void**)&att, g_att);
    cudaGetSymbolAddress((void**)&x,   g_x);
    cudaGetSymbolAddress((void**)&sh,  g_srch);
    cudaGetSymbolAddress((void**)&xh,  g_xh);
    cudaGetSymbolAddress((void**)&ffh, g_ffh);
    cudaGetSymbolAddress((void**)&wqt, g_wqt);
    cudaGetSymbolAddress((void**)&wkt, g_wkt);
    cudaGetSymbolAddress((void**)&wvt, g_wvt);
    cudaGetSymbolAddress((void**)&w1t, g_w1t);
    cudaGetSymbolAddress((void**)&w2t, g_w2t);

    // pre-pass: operand conversion
    to_half<<<SB * DM / 4 / 256, 256>>>(src, sh, SB * DM / 4);
    dim3 tb(32, 8);
    transpose_half<<<dim3(DM / 32, DM / 32),  tb>>>(q_w, wqt, DM, DM);
    transpose_half<<<dim3(DM / 32, DM / 32),  tb>>>(k_w, wkt, DM, DM);
    transpose_half<<<dim3(DM / 32, DM / 32),  tb>>>(v_w, wvt, DM, DM);
    transpose_half<<<dim3(DFF / 32, DM / 32), tb>>>(w1, w1t, DM, DFF);
    transpose_half<<<dim3(DM / 32, DFF / 32), tb>>>(w2, w2t, DFF, DM);

    // QKV
    dim3 gQKV(DM / 128, SB / 128);
    gemm_fp16<0,0><<<gQKV, 256>>>(sh, wqt, q_b, q, nullptr, SB, DM, DM);
    gemm_fp16<0,0><<<gQKV, 256>>>(sh, wkt, k_b, k, nullptr, SB, DM, DM);
    gemm_fp16<0,0><<<gQKV, 256>>>(sh, wvt, v_b, v, nullptr, SB, DM, DM);

    rope_kernel<<<(SB * DM / 2 + 255) / 256, 256>>>(q, k);
    attn_mma<<<dim3(SEQ / 128, NH, BATCH), 256>>>(q, k, v, att);
    add_ln_kernel<1><<<SB, 256>>>(src, att, ln1g, ln1b, x, xh);

    // FFN
    gemm_fp16<1,1><<<dim3(DFF / 128, SB / 128), 256>>>(
        xh, w1t, b1, nullptr, ffh, SB, DFF, DM);
    gemm_fp16<0,0><<<dim3(DM / 128, SB / 128), 256>>>(
        ffh, w2t, b2, att, nullptr, SB, DM, DFF);

    add_ln_kernel<0><<<SB, 256>>>(x, att, ln2g, ln2b, out, nullptr);
}

// round 7
// speedup vs baseline: 8.0745x; 1.1704x over previous
#include <cuda_runtime.h>
#include <cuda_fp16.h>
#include <math.h>
#include <stdint.h>

#define SEQ    2048
#define BATCH  2
#define DM     1024
#define NH     16
#define HD     64
#define DFF    4096
#define SB     (SEQ*BATCH)          /* 4096 rows */
#define LN_EPS 1e-5f

// ---------------- scratch (static __device__, allocation-rule safe) ---------
__device__ float g_att[SB*DM];
__device__ float g_x [SB*DM];

__device__ __half g_srch[SB*DM];
__device__ __half g_xh  [SB*DM];
__device__ __half g_ffh [SB*DFF];
__device__ __half g_qh  [SB*DM];
__device__ __half g_kh  [SB*DM];
__device__ __half g_vh  [SB*DM];
__device__ __half g_wqkvt[3*DM*DM];   // [3072][1024] pre-transposed
__device__ __half g_w1t [DFF*DM];
__device__ __half g_w2t [DM*DFF];
__device__ float2 g_rope[SEQ*32];     // cos/sin per (s, pair)

// ---------------- helpers ---------------------------------------------------
__device__ __forceinline__ unsigned pack_half2(float lo, float hi) {
    __half2 h = __floats2half2_rn(lo, hi);
    return reinterpret_cast<unsigned&>(h);
}
__device__ __forceinline__ void cp16(unsigned dst, const void* gmem) {
    asm volatile("cp.async.cg.shared.global [%0], [%1], 16;" :: "r"(dst), "l"(gmem));
}
__device__ __forceinline__ unsigned smem_u32(const void* p) {
    return (unsigned)__cvta_generic_to_shared(p);
}
__device__ __forceinline__ void mma_fp16(float c[4],
                                         unsigned a0, unsigned a1, unsigned a2, unsigned a3,
                                         unsigned b0, unsigned b1) {
    asm volatile(
        "mma.sync.aligned.m16n8k16.row.col.f32.f16.f16.f32 "
        "{%0,%1,%2,%3}, {%4,%5,%6,%7}, {%8,%9}, {%0,%1,%2,%3};"
        : "+f"(c[0]), "+f"(c[1]), "+f"(c[2]), "+f"(c[3])
        : "r"(a0), "r"(a1), "r"(a2), "r"(a3), "r"(b0), "r"(b1));
}
__device__ __forceinline__ void ldsm_x4(unsigned r[4], unsigned addr) {
    asm volatile("ldmatrix.sync.aligned.m8n8.x4.shared.b16 {%0,%1,%2,%3}, [%4];"
                 : "=r"(r[0]), "=r"(r[1]), "=r"(r[2]), "=r"(r[3]) : "r"(addr));
}
__device__ __forceinline__ void ldsm_x4_t(unsigned r[4], unsigned addr) {
    asm volatile("ldmatrix.sync.aligned.m8n8.x4.trans.shared.b16 {%0,%1,%2,%3}, [%4];"
                 : "=r"(r[0]), "=r"(r[1]), "=r"(r[2]), "=r"(r[3]) : "r"(addr));
}

// ================= GEMM mainloop core (shared by both gemm kernels) =========
// smem: As/Bs [2][128][20] u32 (fp16 pairs along K), 2-stage cp.async, BK=32.
#define GEMM_PROLOG(Aptr, Btptr, Kdim)                                           \
    __shared__ unsigned As[2][128][20];                                          \
    __shared__ unsigned Bs[2][128][20];                                          \
    const int tid  = threadIdx.x;                                                \
    const int warp = tid >> 5, lane = tid & 31;                                  \
    const int g = lane >> 2, t = lane & 3;                                       \
    const int wm = warp >> 1, wn = warp & 1;                                     \
    const int bm = blockIdx.y * 128, bn = blockIdx.x * 128;                      \
    float acc[2][8][4];                                                          \
    _Pragma("unroll") for (int i = 0; i < 2; i++)                                \
        _Pragma("unroll") for (int j = 0; j < 8; j++)                            \
            _Pragma("unroll") for (int r = 0; r < 4; r++) acc[i][j][r] = 0.f;    \
    const int NC = (Kdim) >> 5;                                                  \
    auto load_stage = [&](int s, int kt) {                                       \
        _Pragma("unroll")                                                        \
        for (int u = 0; u < 2; u++) {                                            \
            int f = tid + u * 256;                                               \
            int r = f >> 2, j = f & 3;                                           \
            cp16(smem_u32(&As[s][r][j * 4]), (Aptr)  + (size_t)(bm + r) * (Kdim) + kt + j * 8); \
            cp16(smem_u32(&Bs[s][r][j * 4]), (Btptr) + (size_t)(bn + r) * (Kdim) + kt + j * 8); \
        }                                                                        \
        asm volatile("cp.async.commit_group;");                                  \
    };                                                                           \
    load_stage(0, 0);                                                            \
    for (int c = 0; c < NC; c++) {                                               \
        if (c + 1 < NC) {                                                        \
            load_stage((c + 1) & 1, (c + 1) * 32);                               \
            asm volatile("cp.async.wait_group 1;");                              \
        } else {                                                                 \
            asm volatile("cp.async.wait_group 0;");                              \
        }                                                                        \
        __syncthreads();                                                         \
        const int s = c & 1;                                                     \
        _Pragma("unroll")                                                        \
        for (int ks = 0; ks < 2; ks++) {                                         \
            const int kp = ks * 8;                                               \
            unsigned a[2][4];                                                    \
            _Pragma("unroll")                                                    \
            for (int mf = 0; mf < 2; mf++) {                                     \
                int m = wm * 32 + mf * 16;                                       \
                ldsm_x4(a[mf], smem_u32(&As[s][m + (lane & 15)][kp + ((lane >> 4) << 2)])); \
            }                                                                    \
            _Pragma("unroll")                                                    \
            for (int np = 0; np < 4; np++) {                                     \
                int n = wn * 64 + np * 16;                                       \
                unsigned bf[4];                                                  \
                ldsm_x4(bf, smem_u32(&Bs[s][n + (lane & 7) + ((lane >> 4) << 3)][kp + (((lane >> 3) & 1) << 2)])); \
                mma_fp16(acc[0][np*2],   a[0][0], a[0][1], a[0][2], a[0][3], bf[0], bf[1]); \
                mma_fp16(acc[0][np*2+1], a[0][0], a[0][1], a[0][2], a[0][3], bf[2], bf[3]); \
                mma_fp16(acc[1][np*2],   a[1][0], a[1][1], a[1][2], a[1][3], bf[0], bf[1]); \
                mma_fp16(acc[1][np*2+1], a[1][0], a[1][1], a[1][2], a[1][3], bf[2], bf[3]); \
            }                                                                    \
        }                                                                        \
        __syncthreads();                                                         \
    }

// ---------------- generic GEMM (FFN): C = A@Bt^T + bias ---------------------
template<int RELU, int HALF_OUT>
__global__ __launch_bounds__(256, 2)
void gemm_fp16(const __half* __restrict__ A, const __half* __restrict__ Bt,
               const float* __restrict__ bias,
               float* __restrict__ Cf, __half* __restrict__ Ch,
               int M, int N, int K)
{
    GEMM_PROLOG(A, Bt, K)

    #pragma unroll
    for (int mf = 0; mf < 2; mf++) {
        int r0 = bm + wm * 32 + mf * 16 + g;
        #pragma unroll
        for (int nf = 0; nf < 8; nf++) {
            int col = bn + wn * 64 + nf * 8 + 2 * t;
            float2 bv = *(const float2*)(bias + col);
            float v0 = acc[mf][nf][0] + bv.x;
            float v1 = acc[mf][nf][1] + bv.y;
            float v2 = acc[mf][nf][2] + bv.x;
            float v3 = acc[mf][nf][3] + bv.y;
            if (RELU) {
                v0 = fmaxf(v0, 0.f); v1 = fmaxf(v1, 0.f);
                v2 = fmaxf(v2, 0.f); v3 = fmaxf(v3, 0.f);
            }
            if (HALF_OUT) {
                *(__half2*)(Ch + (size_t)r0       * N + col) = __floats2half2_rn(v0, v1);
                *(__half2*)(Ch + (size_t)(r0 + 8) * N + col) = __floats2half2_rn(v2, v3);
            } else {
                *(float2*)(Cf + (size_t)r0       * N + col) = make_float2(v0, v1);
                *(float2*)(Cf + (size_t)(r0 + 8) * N + col) = make_float2(v2, v3);
            }
        }
    }
}

// ---------------- fused QKV GEMM: rope(q,k) + fp16 stores -------------------
// A = src fp16 [4096,1024]; Bt = wqkvt [3072,1024]. Section by bn (8 blocks each).
__global__ __launch_bounds__(256, 2)
void gemm_qkv(const __half* __restrict__ A, const __half* __restrict__ Bt,
              const float* __restrict__ q_b, const float* __restrict__ k_b,
              const float* __restrict__ v_b,
              const float2* __restrict__ tbl,
              __half* __restrict__ Qh, __half* __restrict__ Kh,
              __half* __restrict__ Vh)
{
    GEMM_PROLOG(A, Bt, DM)

    const int sec   = blockIdx.x >> 3;          // 0=q 1=k 2=v
    const int ncol0 = bn & 1023;
    const float* bias = sec == 0 ? q_b : (sec == 1 ? k_b : v_b);
    __half* outp      = sec == 0 ? Qh  : (sec == 1 ? Kh  : Vh);
    const bool dorope = sec < 2;

    #pragma unroll
    for (int mf = 0; mf < 2; mf++) {
        int r0 = bm + wm * 32 + mf * 16 + g;
        int s0 = r0 >> 1, s1 = (r0 + 8) >> 1;     // BATCH=2: seq pos
        #pragma unroll
        for (int nf = 0; nf < 8; nf++) {
            int col = ncol0 + wn * 64 + nf * 8 + 2 * t;
            float2 bv = *(const float2*)(bias + col);
            float v0 = acc[mf][nf][0] + bv.x;
            float v1 = acc[mf][nf][1] + bv.y;
            float v2 = acc[mf][nf][2] + bv.x;
            float v3 = acc[mf][nf][3] + bv.y;
            if (dorope) {
                int p = (col & 63) >> 1;
                float2 cs0 = tbl[s0 * 32 + p];
                float2 cs1 = tbl[s1 * 32 + p];
                float t0 = v0 * cs0.x - v1 * cs0.y;
                v1 = v1 * cs0.x + v0 * cs0.y; v0 = t0;
                float t2 = v2 * cs1.x - v3 * cs1.y;
                v3 = v3 * cs1.x + v2 * cs1.y; v2 = t2;
            }
            *(__half2*)(outp + (size_t)r0       * DM + col) = __floats2half2_rn(v0, v1);
            *(__half2*)(outp + (size_t)(r0 + 8) * DM + col) = __floats2half2_rn(v2, v3);
        }
    }
}

// ---------------- pre-pass kernels ------------------------------------------
__global__ void to_half(const float* __restrict__ X, __half* __restrict__ H, int n4)
{
    int i = blockIdx.x * blockDim.x + threadIdx.x;
    if (i >= n4) return;
    float4 v = *(const float4*)(X + i * 4);
    *(__half2*)(H + i * 4)     = __floats2half2_rn(v.x, v.y);
    *(__half2*)(H + i * 4 + 2) = __floats2half2_rn(v.z, v.w);
}

__global__ void transpose_half(const float* __restrict__ W, __half* __restrict__ T,
                               int K, int N)
{
    __shared__ float tl[32][33];
    int n0 = blockIdx.x * 32, k0 = blockIdx.y * 32;
    int x = threadIdx.x, y = threadIdx.y;
    #pragma unroll
    for (int i = 0; i < 4; i++) {
        int r = y + i * 8;
        tl[r][x] = W[(size_t)(k0 + r) * N + n0 + x];
    }
    __syncthreads();
    #pragma unroll
    for (int i = 0; i < 4; i++) {
        int r = y + i * 8;
        T[(size_t)(n0 + r) * K + k0 + x] = __float2half_rn(tl[x][r]);
    }
}

__global__ void rope_table(float2* __restrict__ tbl)
{
    int i = blockIdx.x * blockDim.x + threadIdx.x;
    if (i >= SEQ * 32) return;
    int s = i >> 5, p = i & 31;
    float ang = (float)s * powf(10000.0f, -(float)p / 32.0f);
    tbl[i] = make_float2(cosf(ang), sinf(ang));
}

// ---------------- tensor-core flash attention (fp16 in, LDSM) ---------------
// Grid (SEQ/128, NH, BATCH), 256 thr = 8 warps, warp owns 16 q-rows.
__global__ __launch_bounds__(256)
void attn_mma(const __half* __restrict__ Q, const __half* __restrict__ K,
              const __half* __restrict__ V, float* __restrict__ O)
{
    const int qt = blockIdx.x, h = blockIdx.y, b = blockIdx.z;
    const int stride = BATCH * DM;
    const size_t base = (size_t)b * DM + h * HD;
    const int tid = threadIdx.x;
    const int w = tid >> 5, lane = tid & 31;
    const int g = lane >> 2, t = lane & 3;
    const int qrow0 = qt * 128 + w * 16 + g;

    __shared__ unsigned Ks[64][36];   // u32 view of fp16 [64][72-pad]
    __shared__ __half   Vs[64][72];   // fp16 rows (64 data + 8 pad), stride 144B

    // Q fragments straight from fp16 gmem
    unsigned qf[4][4];
    {
        const __half* Qr0 = Q + (size_t)qrow0 * stride + base;
        const __half* Qr1 = Qr0 + (size_t)8 * stride;
        #pragma unroll
        for (int c = 0; c < 4; c++) {
            qf[c][0] = *(const unsigned*)(Qr0 + 16*c + 2*t);
            qf[c][1] = *(const unsigned*)(Qr1 + 16*c + 2*t);
            qf[c][2] = *(const unsigned*)(Qr0 + 16*c + 8 + 2*t);
            qf[c][3] = *(const unsigned*)(Qr1 + 16*c + 8 + 2*t);
        }
    }

    float oacc[8][4];
    #pragma unroll
    for (int n = 0; n < 8; n++)
        #pragma unroll
        for (int r = 0; r < 4; r++) oacc[n][r] = 0.f;
    float m0 = -1e30f, m1 = -1e30f, l0 = 0.f, l1 = 0.f;

    for (int kt = 0; kt < SEQ; kt += 64) {
        __syncthreads();
        const __half* Kg = K + (size_t)kt * stride + base;
        const __half* Vg = V + (size_t)kt * stride + base;
        for (int i = tid; i < 512; i += 256) {
            int r = i >> 3, j = i & 7;
            *(float4*)&Ks[r][j * 4] = *(const float4*)(Kg + (size_t)r * stride + j * 8);
            *(float4*)&Vs[r][j * 8] = *(const float4*)(Vg + (size_t)r * stride + j * 8);
        }
        __syncthreads();

        // ---- S = Q @ K^T ----
        float sacc[8][4];
        #pragma unroll
        for (int n = 0; n < 8; n++)
            #pragma unroll
            for (int r = 0; r < 4; r++) sacc[n][r] = 0.f;

        #pragma unroll
        for (int c = 0; c < 4; c++) {
            #pragma unroll
            for (int np = 0; np < 4; np++) {
                unsigned kf[4];
                ldsm_x4(kf, smem_u32(&Ks[np*16 + (lane & 7) + ((lane >> 4) << 3)]
                                        [c*8 + (((lane >> 3) & 1) << 2)]));
                mma_fp16(sacc[np*2],   qf[c][0], qf[c][1], qf[c][2], qf[c][3], kf[0], kf[1]);
                mma_fp16(sacc[np*2+1], qf[c][0], qf[c][1], qf[c][2], qf[c][3], kf[2], kf[3]);
            }
        }

        // ---- online softmax ----
        float mx0 = -1e30f, mx1 = -1e30f;
        #pragma unroll
        for (int n = 0; n < 8; n++) {
            sacc[n][0] *= 0.125f; sacc[n][1] *= 0.125f;
            sacc[n][2] *= 0.125f; sacc[n][3] *= 0.125f;
            mx0 = fmaxf(mx0, fmaxf(sacc[n][0], sacc[n][1]));
            mx1 = fmaxf(mx1, fmaxf(sacc[n][2], sacc[n][3]));
        }
        mx0 = fmaxf(mx0, __shfl_xor_sync(0xFFFFFFFFu, mx0, 1));
        mx0 = fmaxf(mx0, __shfl_xor_sync(0xFFFFFFFFu, mx0, 2));
        mx1 = fmaxf(mx1, __shfl_xor_sync(0xFFFFFFFFu, mx1, 1));
        mx1 = fmaxf(mx1, __shfl_xor_sync(0xFFFFFFFFu, mx1, 2));

        float nm0 = fmaxf(m0, mx0), nm1 = fmaxf(m1, mx1);
        float sc0 = __expf(m0 - nm0), sc1 = __expf(m1 - nm1);
        m0 = nm0; m1 = nm1;

        float rs0 = 0.f, rs1 = 0.f;
        unsigned pa[4][4];
        #pragma unroll
        for (int n = 0; n < 8; n++) {
            float p0 = __expf(sacc[n][0] - nm0);
            float p1 = __expf(sacc[n][1] - nm0);
            float p2 = __expf(sacc[n][2] - nm1);
            float p3 = __expf(sacc[n][3] - nm1);
            rs0 += p0 + p1; rs1 += p2 + p3;
            int kk = n >> 1, half = n & 1;
            pa[kk][half*2 + 0] = pack_half2(p0, p1);
            pa[kk][half*2 + 1] = pack_half2(p2, p3);
        }
        rs0 += __shfl_xor_sync(0xFFFFFFFFu, rs0, 1);
        rs0 += __shfl_xor_sync(0xFFFFFFFFu, rs0, 2);
        rs1 += __shfl_xor_sync(0xFFFFFFFFu, rs1, 1);
        rs1 += __shfl_xor_sync(0xFFFFFFFFu, rs1, 2);
        l0 = l0 * sc0 + rs0;
        l1 = l1 * sc1 + rs1;

        #pragma unroll
        for (int n = 0; n < 8; n++) {
            oacc[n][0] *= sc0; oacc[n][1] *= sc0;
            oacc[n][2] *= sc1; oacc[n][3] *= sc1;
        }

        // ---- O += P @ V (V frags via ldmatrix.trans) ----
        #pragma unroll
        for (int kk = 0; kk < 4; kk++) {
            #pragma unroll
            for (int nn = 0; nn < 8; nn += 2) {
                unsigned vf[4];
                ldsm_x4_t(vf, smem_u32(&Vs[kk*16 + (lane & 15)][(nn + (lane >> 4)) * 8]));
                mma_fp16(oacc[nn],   pa[kk][0], pa[kk][1], pa[kk][2], pa[kk][3], vf[0], vf[1]);
                mma_fp16(oacc[nn+1], pa[kk][0], pa[kk][1], pa[kk][2], pa[kk][3], vf[2], vf[3]);
            }
        }
    }

    float inv0 = 1.f / l0, inv1 = 1.f / l1;
    float* Or0 = O + (size_t)qrow0 * stride + base;
    float* Or1 = Or0 + (size_t)8 * stride;
    #pragma unroll
    for (int nn = 0; nn < 8; nn++) {
        float2 v0 = { oacc[nn][0] * inv0, oacc[nn][1] * inv0 };
        float2 v1 = { oacc[nn][2] * inv1, oacc[nn][3] * inv1 };
        *(float2*)(Or0 + nn*8 + 2*t) = v0;
        *(float2*)(Or1 + nn*8 + 2*t) = v1;
    }
}

// ---------------- residual add + LayerNorm (+ optional fp16 copy out) -------
template<int HALF>
__global__ __launch_bounds__(256)
void add_ln_kernel(const float* __restrict__ A, const float* __restrict__ B,
                   const float* __restrict__ g, const float* __restrict__ bta,
                   float* __restrict__ out, __half* __restrict__ oh)
{
    const int row = blockIdx.x;
    const int tid = threadIdx.x;
    const float* a = A + (size_t)row * DM;
    const float* b = B + (size_t)row * DM;

    float v[4];
    float4 va = *(const float4*)(a + tid * 4);
    float4 vb = *(const float4*)(b + tid * 4);
    v[0] = va.x + vb.x; v[1] = va.y + vb.y;
    v[2] = va.z + vb.z; v[3] = va.w + vb.w;

    float sum = v[0] + v[1] + v[2] + v[3];
    float sq  = v[0]*v[0] + v[1]*v[1] + v[2]*v[2] + v[3]*v[3];

    #pragma unroll
    for (int off = 16; off; off >>= 1) {
        sum += __shfl_xor_sync(0xFFFFFFFF, sum, off);
        sq  += __shfl_xor_sync(0xFFFFFFFF, sq,  off);
    }
    __shared__ float ssum[8], ssq[8], sstat[2];
    if ((tid & 31) == 0) { ssum[tid >> 5] = sum; ssq[tid >> 5] = sq; }
    __syncthreads();
    if (tid == 0) {
        float ts = 0.f, tq = 0.f;
        #pragma unroll
        for (int i = 0; i < 8; i++) { ts += ssum[i]; tq += ssq[i]; }
        float mean = ts / (float)DM;
        float var  = tq / (float)DM - mean * mean;
        sstat[0] = mean;
        sstat[1] = rsqrtf(fmaxf(var, 0.f) + LN_EPS);
    }
    __syncthreads();
    float mean = sstat[0], inv = sstat[1];

    float4 vg = *(const float4*)(g   + tid * 4);
    float4 vB = *(const float4*)(bta + tid * 4);
    float4 r;
    r.x = (v[0] - mean) * inv * vg.x + vB.x;
    r.y = (v[1] - mean) * inv * vg.y + vB.y;
    r.z = (v[2] - mean) * inv * vg.z + vB.z;
    r.w = (v[3] - mean) * inv * vg.w + vB.w;
    *(float4*)(out + (size_t)row * DM + tid * 4) = r;

    if (HALF) {
        *(__half2*)(oh + (size_t)row * DM + tid * 4)     = __floats2half2_rn(r.x, r.y);
        *(__half2*)(oh + (size_t)row * DM + tid * 4 + 2) = __floats2half2_rn(r.z, r.w);
    }
}

// ---------------------------------------------------------------------------
extern "C" void kernel_launch(void* const* d_in, const int* in_sizes, int n_in,
                              void* d_out, int out_size)
{
    const float* src  = (const float*)d_in[0];
    const float* q_w  = (const float*)d_in[1];
    const float* q_b  = (const float*)d_in[2];
    const float* k_w  = (const float*)d_in[3];
    const float* k_b  = (const float*)d_in[4];
    const float* v_w  = (const float*)d_in[5];
    const float* v_b  = (const float*)d_in[6];
    const float* w1   = (const float*)d_in[7];
    const float* b1   = (const float*)d_in[8];
    const float* w2   = (const float*)d_in[9];
    const float* b2   = (const float*)d_in[10];
    const float* ln1g = (const float*)d_in[11];
    const float* ln1b = (const float*)d_in[12];
    const float* ln2g = (const float*)d_in[13];
    const float* ln2b = (const float*)d_in[14];
    float* out = (float*)d_out;

    float *att, *x;
    float2* tbl;
    __half *sh, *xh, *ffh, *qh, *kh, *vh, *wqkvt, *w1t, *w2t;
    cudaGetSymbolAddress((void**)&att,   g_att);
    cudaGetSymbolAddress((void**)&x,     g_x);
    cudaGetSymbolAddress((void**)&sh,    g_srch);
    cudaGetSymbolAddress((void**)&xh,    g_xh);
    cudaGetSymbolAddress((void**)&ffh,   g_ffh);
    cudaGetSymbolAddress((void**)&qh,    g_qh);
    cudaGetSymbolAddress((void**)&kh,    g_kh);
    cudaGetSymbolAddress((void**)&vh,    g_vh);
    cudaGetSymbolAddress((void**)&wqkvt, g_wqkvt);
    cudaGetSymbolAddress((void**)&w1t,   g_w1t);
    cudaGetSymbolAddress((void**)&w2t,   g_w2t);
    cudaGetSymbolAddress((void**)&tbl,   g_rope);

    // pre-pass
    to_half<<<SB * DM / 4 / 256, 256>>>(src, sh, SB * DM / 4);
    dim3 tb(32, 8);
    transpose_half<<<dim3(DM / 32, DM / 32),  tb>>>(q_w, wqkvt,               DM, DM);
    transpose_half<<<dim3(DM / 32, DM / 32),  tb>>>(k_w, wqkvt + DM * DM,     DM, DM);
    transpose_half<<<dim3(DM / 32, DM / 32),  tb>>>(v_w, wqkvt + 2 * DM * DM, DM, DM);
    transpose_half<<<dim3(DFF / 32, DM / 32), tb>>>(w1, w1t, DM, DFF);
    transpose_half<<<dim3(DM / 32, DFF / 32), tb>>>(w2, w2t, DFF, DM);
    rope_table<<<SEQ * 32 / 256, 256>>>(tbl);

    // fused QKV (+bias +rope) -> fp16 q,k,v
    gemm_qkv<<<dim3(3 * DM / 128, SB / 128), 256>>>(sh, wqkvt, q_b, k_b, v_b,
                                                    tbl, qh, kh, vh);

    attn_mma<<<dim3(SEQ / 128, NH, BATCH), 256>>>(qh, kh, vh, att);
    add_ln_kernel<1><<<SB, 256>>>(src, att, ln1g, ln1b, x, xh);

    // FFN
    gemm_fp16<1,1><<<dim3(DFF / 128, SB / 128), 256>>>(
        xh, w1t, b1, nullptr, ffh, SB, DFF, DM);
    gemm_fp16<0,0><<<dim3(DM / 128, SB / 128), 256>>>(
        ffh, w2t, b2, att, nullptr, SB, DM, DFF);

    add_ln_kernel<0><<<SB, 256>>>(x, att, ln2g, ln2b, out, nullptr);
}